// round 10
// baseline (speedup 1.0000x reference)
#include <cuda_runtime.h>
#include <cuda_fp16.h>
#include <cstdint>

// Mosaic GEMM via fp16 HMMA: 2 CTAs/SM, 4 warps/CTA, warp tile 32x64
// (halves A-fragment smem re-reads), 4-stage cp.async, 1 sync/chunk.
//   out[256,8192] = x @ W + bias,  W[k,n] = blocks[parts[k/64,n/64]][k%64][n%64]

#define KDIM 8192
#define NDIM 8192
#define BROWS 256
#define TM 64
#define TN 128
#define TK 64
#define NCHUNK 128          // KDIM / TK
#define THREADS 128

#define A_STRIDE_B 144      // 64 halves + 8 pad   (144 % 128 == 16 -> conflict-free)
#define B_STRIDE_B 272      // 128 halves + 8 pad  (272 % 128 == 16 -> conflict-free)
#define A_BYTES (TM * A_STRIDE_B)          // 9216
#define B_BYTES (TK * B_STRIDE_B)          // 17408
#define STAGE_BYTES (A_BYTES + B_BYTES)    // 26624
#define NSTAGE 4
#define SMEM_DYN (NSTAGE * STAGE_BYTES)    // 106496 per CTA; 2 CTAs/SM = 212992

static __device__ __half g_xh[BROWS * KDIM];        // fp16 x
static __device__ __half g_wh[1024 * 64 * 64];      // fp16 blocks (native [p][k][n])

// ---------------- helpers ----------------
__device__ __forceinline__ uint32_t smem_u32(const void* p) {
    uint32_t a;
    asm("{ .reg .u64 t; cvta.to.shared.u64 t, %1; cvt.u32.u64 %0, t; }" : "=r"(a) : "l"(p));
    return a;
}
__device__ __forceinline__ void cp16(uint32_t dst, const __half* src) {
    asm volatile("cp.async.cg.shared.global [%0], [%1], 16;"
                 :: "r"(dst), "l"(__cvta_generic_to_global(src)));
}
__device__ __forceinline__ void ldsm4(uint32_t* r, uint32_t addr) {
    asm volatile("ldmatrix.sync.aligned.m8n8.x4.shared.b16 {%0,%1,%2,%3}, [%4];"
        : "=r"(r[0]), "=r"(r[1]), "=r"(r[2]), "=r"(r[3]) : "r"(addr));
}
__device__ __forceinline__ void ldsm4t(uint32_t* r, uint32_t addr) {
    asm volatile("ldmatrix.sync.aligned.m8n8.x4.trans.shared.b16 {%0,%1,%2,%3}, [%4];"
        : "=r"(r[0]), "=r"(r[1]), "=r"(r[2]), "=r"(r[3]) : "r"(addr));
}
__device__ __forceinline__ void mma16816(float* c, const uint32_t* a,
                                         uint32_t b0, uint32_t b1) {
    asm volatile(
        "mma.sync.aligned.m16n8k16.row.col.f32.f16.f16.f32 "
        "{%0,%1,%2,%3}, {%4,%5,%6,%7}, {%8,%9}, {%0,%1,%2,%3};"
        : "+f"(c[0]), "+f"(c[1]), "+f"(c[2]), "+f"(c[3])
        : "r"(a[0]), "r"(a[1]), "r"(a[2]), "r"(a[3]), "r"(b0), "r"(b1));
}

// ---------------- fused conversion kernel ----------------
__global__ void convert_all_kernel(const float* __restrict__ x,
                                   const float* __restrict__ blocks) {
    const int b = blockIdx.x;
    if (b < 2048) {
        const int i = (b * 256 + threadIdx.x) * 4;
        const float4 v = *reinterpret_cast<const float4*>(x + i);
        *reinterpret_cast<__half2*>(g_xh + i)     = __floats2half2_rn(v.x, v.y);
        *reinterpret_cast<__half2*>(g_xh + i + 2) = __floats2half2_rn(v.z, v.w);
    } else {
        const size_t i = ((size_t)(b - 2048) * 256 + threadIdx.x) * 4;
        const float4 v = *reinterpret_cast<const float4*>(blocks + i);
        *reinterpret_cast<__half2*>(g_wh + i)     = __floats2half2_rn(v.x, v.y);
        *reinterpret_cast<__half2*>(g_wh + i + 2) = __floats2half2_rn(v.z, v.w);
    }
}

// ---------------- main kernel ----------------
__global__ void __launch_bounds__(THREADS, 2)
mosaic_hmma_kernel(const int* __restrict__ parts,
                   const float* __restrict__ bias,
                   float* __restrict__ out)
{
    extern __shared__ __align__(128) char smem[];
    const uint32_t sb = smem_u32(smem);
    const int tid  = threadIdx.x;
    const int wid  = tid >> 5;
    const int lane = tid & 31;
    const int m0 = blockIdx.y * TM;
    const int n0 = blockIdx.x * TN;
    const int o0 = blockIdx.x * 2;

    const int wm = (wid & 1) * 32;     // 2 warp-rows
    const int wn = (wid >> 1) * 64;    // 2 warp-cols, warp tile 32x64
    const int lrow = lane & 15;
    const int lcol = (lane >> 4) * 8;

    float acc[2][8][4];                // [m16-group][n8-group][frag]
    #pragma unroll
    for (int a = 0; a < 2; ++a)
        #pragma unroll
        for (int b = 0; b < 8; ++b)
            #pragma unroll
            for (int c = 0; c < 4; ++c) acc[a][b][c] = 0.f;

    // cp.async mappings (128 threads)
    const int ar = tid >> 3, ac = tid & 7;    // A: rows ar+16*it (4 it), col-16B ac
    const int br = tid >> 4, bc = tid & 15;   // B: rows br+8*it (8 it), col-16B bc

    auto issue = [&](int i) {
        if (i < NCHUNK) {
            const int s = i & (NSTAGE - 1);
            const uint32_t abase = sb + s * STAGE_BYTES;
            const uint32_t bbase = abase + A_BYTES;
            const int p0 = parts[i * 128 + o0];
            const int p1 = parts[i * 128 + o0 + 1];
            const size_t k0 = (size_t)i * TK;
            const __half* asrc = g_xh + (size_t)(m0 + ar) * KDIM + k0 + ac * 8;
            #pragma unroll
            for (int it = 0; it < 4; ++it)
                cp16(abase + (ar + it * 16) * A_STRIDE_B + ac * 16,
                     asrc + (size_t)it * 16 * KDIM);
            const __half* bsrc = g_wh + ((size_t)((bc < 8) ? p0 : p1) << 12)
                               + br * 64 + (bc & 7) * 8;
            #pragma unroll
            for (int it = 0; it < 8; ++it)
                cp16(bbase + (br + it * 8) * B_STRIDE_B + bc * 16,
                     bsrc + it * 8 * 64);
        }
        asm volatile("cp.async.commit_group;" ::: "memory");
    };

    issue(0); issue(1); issue(2);

    for (int i = 0; i < NCHUNK; ++i) {
        asm volatile("cp.async.wait_group 2;" ::: "memory");
        __syncthreads();
        issue(i + 3);

        const uint32_t abase = sb + (i & (NSTAGE - 1)) * STAGE_BYTES;
        const uint32_t bbase = abase + A_BYTES;
        const uint32_t a_ad = abase + (wm + lrow) * A_STRIDE_B + lcol * 2;
        const uint32_t b_ad = bbase + lrow * B_STRIDE_B + (wn + lcol) * 2;

        #pragma unroll
        for (int kk = 0; kk < 4; ++kk) {               // four k16 steps
            uint32_t af[2][4];
            ldsm4(af[0], a_ad + kk * 32);
            ldsm4(af[1], a_ad + 16 * A_STRIDE_B + kk * 32);
            uint32_t bf[4][4];
            #pragma unroll
            for (int nt = 0; nt < 4; ++nt)
                ldsm4t(bf[nt], b_ad + kk * 16 * B_STRIDE_B + nt * 32);
            #pragma unroll
            for (int mt = 0; mt < 2; ++mt)
                #pragma unroll
                for (int nt = 0; nt < 4; ++nt) {
                    mma16816(acc[mt][nt * 2 + 0], af[mt], bf[nt][0], bf[nt][1]);
                    mma16816(acc[mt][nt * 2 + 1], af[mt], bf[nt][2], bf[nt][3]);
                }
        }
    }

    // -------- epilogue: bias + store --------
    const int qr = lane >> 2;
    const int qc = (lane & 3) * 2;
    #pragma unroll
    for (int mt = 0; mt < 2; ++mt) {
        const size_t r0 = (size_t)(m0 + wm + mt * 16 + qr);
        #pragma unroll
        for (int nj = 0; nj < 8; ++nj) {
            const int col = n0 + wn + nj * 8 + qc;
            const float2 bv = *reinterpret_cast<const float2*>(bias + col);
            float2 lo, hi;
            lo.x = acc[mt][nj][0] + bv.x;  lo.y = acc[mt][nj][1] + bv.y;
            hi.x = acc[mt][nj][2] + bv.x;  hi.y = acc[mt][nj][3] + bv.y;
            *reinterpret_cast<float2*>(out + r0 * NDIM + col)       = lo;
            *reinterpret_cast<float2*>(out + (r0 + 8) * NDIM + col) = hi;
        }
    }
}

// ---------------- launch ----------------
extern "C" void kernel_launch(void* const* d_in, const int* in_sizes, int n_in,
                              void* d_out, int out_size) {
    const float* x      = (const float*)d_in[0];   // [256, 8192]
    const float* blocks = (const float*)d_in[1];   // [1024, 64, 64]
    const float* bias   = (const float*)d_in[2];   // [8192]
    const int*   parts  = (const int*)d_in[3];     // [128, 128]
    float* out = (float*)d_out;                    // [256, 8192]

    convert_all_kernel<<<6144, 256>>>(x, blocks);

    cudaFuncSetAttribute(mosaic_hmma_kernel,
                         cudaFuncAttributeMaxDynamicSharedMemorySize, SMEM_DYN);
    dim3 grid(NDIM / TN, BROWS / TM);   // (64, 4) = 256 CTAs -> 2 per SM
    mosaic_hmma_kernel<<<grid, THREADS, SMEM_DYN>>>(parts, bias, out);
}

// round 11
// speedup vs baseline: 1.2507x; 1.2507x over previous
#include <cuda_runtime.h>
#include <cuda_fp16.h>
#include <cstdint>

// Mosaic GEMM via fp16 HMMA: 2 CTAs/SM x 8 warps (32x32 warp tiles),
// 4-stage TK=64 cp.async pipeline, single __syncthreads per chunk.
//   out[256,8192] = x @ W + bias,  W[k,n] = blocks[parts[k/64,n/64]][k%64][n%64]

#define KDIM 8192
#define NDIM 8192
#define BROWS 256
#define TM 64
#define TN 128
#define TK 64
#define NCHUNK 128          // KDIM / TK
#define THREADS 256

#define A_STRIDE_B 144      // 64 halves + 8 pad   (144 % 128 == 16 -> conflict-free)
#define B_STRIDE_B 272      // 128 halves + 8 pad  (272 % 128 == 16 -> conflict-free)
#define A_BYTES (TM * A_STRIDE_B)          // 9216
#define B_BYTES (TK * B_STRIDE_B)          // 17408
#define STAGE_BYTES (A_BYTES + B_BYTES)    // 26624
#define NSTAGE 4
#define SMEM_DYN (NSTAGE * STAGE_BYTES)    // 106496/CTA; 2 CTAs/SM = 212992

static __device__ __half g_xh[BROWS * KDIM];        // fp16 x
static __device__ __half g_wh[1024 * 64 * 64];      // fp16 blocks (native [p][k][n])

// ---------------- helpers ----------------
__device__ __forceinline__ uint32_t smem_u32(const void* p) {
    uint32_t a;
    asm("{ .reg .u64 t; cvta.to.shared.u64 t, %1; cvt.u32.u64 %0, t; }" : "=r"(a) : "l"(p));
    return a;
}
__device__ __forceinline__ void cp16(uint32_t dst, const __half* src) {
    asm volatile("cp.async.cg.shared.global [%0], [%1], 16;"
                 :: "r"(dst), "l"(__cvta_generic_to_global(src)));
}
__device__ __forceinline__ void ldsm4(uint32_t* r, uint32_t addr) {
    asm volatile("ldmatrix.sync.aligned.m8n8.x4.shared.b16 {%0,%1,%2,%3}, [%4];"
        : "=r"(r[0]), "=r"(r[1]), "=r"(r[2]), "=r"(r[3]) : "r"(addr));
}
__device__ __forceinline__ void ldsm4t(uint32_t* r, uint32_t addr) {
    asm volatile("ldmatrix.sync.aligned.m8n8.x4.trans.shared.b16 {%0,%1,%2,%3}, [%4];"
        : "=r"(r[0]), "=r"(r[1]), "=r"(r[2]), "=r"(r[3]) : "r"(addr));
}
__device__ __forceinline__ void mma16816(float* c, const uint32_t* a,
                                         uint32_t b0, uint32_t b1) {
    asm volatile(
        "mma.sync.aligned.m16n8k16.row.col.f32.f16.f16.f32 "
        "{%0,%1,%2,%3}, {%4,%5,%6,%7}, {%8,%9}, {%0,%1,%2,%3};"
        : "+f"(c[0]), "+f"(c[1]), "+f"(c[2]), "+f"(c[3])
        : "r"(a[0]), "r"(a[1]), "r"(a[2]), "r"(a[3]), "r"(b0), "r"(b1));
}

// ---------------- fused conversion kernel ----------------
__global__ void convert_all_kernel(const float* __restrict__ x,
                                   const float* __restrict__ blocks) {
    const int b = blockIdx.x;
    if (b < 2048) {
        const int i = (b * 256 + threadIdx.x) * 4;
        const float4 v = *reinterpret_cast<const float4*>(x + i);
        *reinterpret_cast<__half2*>(g_xh + i)     = __floats2half2_rn(v.x, v.y);
        *reinterpret_cast<__half2*>(g_xh + i + 2) = __floats2half2_rn(v.z, v.w);
    } else {
        const size_t i = ((size_t)(b - 2048) * 256 + threadIdx.x) * 4;
        const float4 v = *reinterpret_cast<const float4*>(blocks + i);
        *reinterpret_cast<__half2*>(g_wh + i)     = __floats2half2_rn(v.x, v.y);
        *reinterpret_cast<__half2*>(g_wh + i + 2) = __floats2half2_rn(v.z, v.w);
    }
}

// ---------------- main kernel ----------------
__global__ void __launch_bounds__(THREADS, 2)
mosaic_hmma_kernel(const int* __restrict__ parts,
                   const float* __restrict__ bias,
                   float* __restrict__ out)
{
    extern __shared__ __align__(128) char smem[];
    const uint32_t sb = smem_u32(smem);
    const int tid  = threadIdx.x;
    const int wid  = tid >> 5;
    const int lane = tid & 31;
    const int m0 = blockIdx.y * TM;
    const int n0 = blockIdx.x * TN;
    const int o0 = blockIdx.x * 2;

    const int wm = (wid & 1) * 32;      // 2 warp-rows
    const int wn = (wid >> 1) * 32;     // 4 warp-cols (warp tile 32x32)
    const int lrow = lane & 15;
    const int lcol = (lane >> 4) * 8;

    float acc[2][4][4];
    #pragma unroll
    for (int a = 0; a < 2; ++a)
        #pragma unroll
        for (int b = 0; b < 4; ++b)
            #pragma unroll
            for (int c = 0; c < 4; ++c) acc[a][b][c] = 0.f;

    // cp.async mappings (256 threads, TK=64)
    const int ar = tid >> 3, ac = tid & 7;    // A: rows ar, ar+32 ; col-16B ac
    const int br = tid >> 4, bc = tid & 15;   // B: rows br+16*it (4 it); col-16B bc

    auto issue = [&](int i) {
        if (i < NCHUNK) {
            const int s = i & (NSTAGE - 1);
            const uint32_t abase = sb + s * STAGE_BYTES;
            const uint32_t bbase = abase + A_BYTES;
            const int p0 = parts[i * 128 + o0];
            const int p1 = parts[i * 128 + o0 + 1];
            const size_t k0 = (size_t)i * TK;
            const __half* asrc = g_xh + (size_t)(m0 + ar) * KDIM + k0 + ac * 8;
            cp16(abase + ar * A_STRIDE_B + ac * 16, asrc);
            cp16(abase + (ar + 32) * A_STRIDE_B + ac * 16, asrc + (size_t)32 * KDIM);
            const __half* bsrc = g_wh + ((size_t)((bc < 8) ? p0 : p1) << 12)
                               + br * 64 + (bc & 7) * 8;
            #pragma unroll
            for (int it = 0; it < 4; ++it)
                cp16(bbase + (br + it * 16) * B_STRIDE_B + bc * 16,
                     bsrc + it * 16 * 64);
        }
        asm volatile("cp.async.commit_group;" ::: "memory");
    };

    issue(0); issue(1); issue(2);

    for (int i = 0; i < NCHUNK; ++i) {
        asm volatile("cp.async.wait_group 2;" ::: "memory");
        __syncthreads();
        issue(i + 3);

        const uint32_t abase = sb + (i & (NSTAGE - 1)) * STAGE_BYTES;
        const uint32_t bbase = abase + A_BYTES;
        const uint32_t a_ad = abase + (wm + lrow) * A_STRIDE_B + lcol * 2;
        const uint32_t b_ad = bbase + lrow * B_STRIDE_B + (wn + lcol) * 2;

        #pragma unroll
        for (int kk = 0; kk < 4; ++kk) {               // four k16 steps
            uint32_t af[2][4];
            ldsm4(af[0], a_ad + kk * 32);
            ldsm4(af[1], a_ad + 16 * A_STRIDE_B + kk * 32);
            uint32_t bf[2][4];
            #pragma unroll
            for (int nt = 0; nt < 2; ++nt)
                ldsm4t(bf[nt], b_ad + kk * 16 * B_STRIDE_B + nt * 32);
            #pragma unroll
            for (int mt = 0; mt < 2; ++mt)
                #pragma unroll
                for (int nt = 0; nt < 2; ++nt) {
                    mma16816(acc[mt][nt * 2 + 0], af[mt], bf[nt][0], bf[nt][1]);
                    mma16816(acc[mt][nt * 2 + 1], af[mt], bf[nt][2], bf[nt][3]);
                }
        }
    }

    // -------- epilogue: bias + store --------
    const int qr = lane >> 2;
    const int qc = (lane & 3) * 2;
    #pragma unroll
    for (int mt = 0; mt < 2; ++mt) {
        const size_t r0 = (size_t)(m0 + wm + mt * 16 + qr);
        #pragma unroll
        for (int nj = 0; nj < 4; ++nj) {
            const int col = n0 + wn + nj * 8 + qc;
            const float2 bv = *reinterpret_cast<const float2*>(bias + col);
            float2 lo, hi;
            lo.x = acc[mt][nj][0] + bv.x;  lo.y = acc[mt][nj][1] + bv.y;
            hi.x = acc[mt][nj][2] + bv.x;  hi.y = acc[mt][nj][3] + bv.y;
            *reinterpret_cast<float2*>(out + r0 * NDIM + col)       = lo;
            *reinterpret_cast<float2*>(out + (r0 + 8) * NDIM + col) = hi;
        }
    }
}

// ---------------- launch ----------------
extern "C" void kernel_launch(void* const* d_in, const int* in_sizes, int n_in,
                              void* d_out, int out_size) {
    const float* x      = (const float*)d_in[0];   // [256, 8192]
    const float* blocks = (const float*)d_in[1];   // [1024, 64, 64]
    const float* bias   = (const float*)d_in[2];   // [8192]
    const int*   parts  = (const int*)d_in[3];     // [128, 128]
    float* out = (float*)d_out;                    // [256, 8192]

    convert_all_kernel<<<6144, 256>>>(x, blocks);

    cudaFuncSetAttribute(mosaic_hmma_kernel,
                         cudaFuncAttributeMaxDynamicSharedMemorySize, SMEM_DYN);
    dim3 grid(NDIM / TN, BROWS / TM);   // (64, 4) = 256 CTAs -> 2 per SM
    mosaic_hmma_kernel<<<grid, THREADS, SMEM_DYN>>>(parts, bias, out);
}

// round 12
// speedup vs baseline: 1.2554x; 1.0038x over previous
#include <cuda_runtime.h>
#include <cuda_fp16.h>
#include <cstdint>

// Mosaic GEMM via fp16 HMMA: 2 CTAs/SM x 8 warps (32x32 warp tiles),
// 4-stage TK=64 cp.async pipeline, 1 sync/chunk, register-double-buffered
// ldmatrix fragments (prefetch kk+1 during mma kk).
//   out[256,8192] = x @ W + bias,  W[k,n] = blocks[parts[k/64,n/64]][k%64][n%64]

#define KDIM 8192
#define NDIM 8192
#define BROWS 256
#define TM 64
#define TN 128
#define TK 64
#define NCHUNK 128          // KDIM / TK
#define THREADS 256

#define A_STRIDE_B 144      // 64 halves + 8 pad   (144 % 128 == 16 -> conflict-free)
#define B_STRIDE_B 272      // 128 halves + 8 pad  (272 % 128 == 16 -> conflict-free)
#define A_BYTES (TM * A_STRIDE_B)          // 9216
#define B_BYTES (TK * B_STRIDE_B)          // 17408
#define STAGE_BYTES (A_BYTES + B_BYTES)    // 26624
#define NSTAGE 4
#define SMEM_DYN (NSTAGE * STAGE_BYTES)    // 106496/CTA; 2 CTAs/SM = 212992

static __device__ __half g_xh[BROWS * KDIM];        // fp16 x
static __device__ __half g_wh[1024 * 64 * 64];      // fp16 blocks (native [p][k][n])

// ---------------- helpers ----------------
__device__ __forceinline__ uint32_t smem_u32(const void* p) {
    uint32_t a;
    asm("{ .reg .u64 t; cvta.to.shared.u64 t, %1; cvt.u32.u64 %0, t; }" : "=r"(a) : "l"(p));
    return a;
}
__device__ __forceinline__ void cp16(uint32_t dst, const __half* src) {
    asm volatile("cp.async.cg.shared.global [%0], [%1], 16;"
                 :: "r"(dst), "l"(__cvta_generic_to_global(src)));
}
__device__ __forceinline__ void ldsm4(uint32_t* r, uint32_t addr) {
    asm volatile("ldmatrix.sync.aligned.m8n8.x4.shared.b16 {%0,%1,%2,%3}, [%4];"
        : "=r"(r[0]), "=r"(r[1]), "=r"(r[2]), "=r"(r[3]) : "r"(addr));
}
__device__ __forceinline__ void ldsm4t(uint32_t* r, uint32_t addr) {
    asm volatile("ldmatrix.sync.aligned.m8n8.x4.trans.shared.b16 {%0,%1,%2,%3}, [%4];"
        : "=r"(r[0]), "=r"(r[1]), "=r"(r[2]), "=r"(r[3]) : "r"(addr));
}
__device__ __forceinline__ void mma16816(float* c, const uint32_t* a,
                                         uint32_t b0, uint32_t b1) {
    asm volatile(
        "mma.sync.aligned.m16n8k16.row.col.f32.f16.f16.f32 "
        "{%0,%1,%2,%3}, {%4,%5,%6,%7}, {%8,%9}, {%0,%1,%2,%3};"
        : "+f"(c[0]), "+f"(c[1]), "+f"(c[2]), "+f"(c[3])
        : "r"(a[0]), "r"(a[1]), "r"(a[2]), "r"(a[3]), "r"(b0), "r"(b1));
}

// ---------------- fused conversion kernel ----------------
__global__ void convert_all_kernel(const float* __restrict__ x,
                                   const float* __restrict__ blocks) {
    const int b = blockIdx.x;
    if (b < 2048) {
        const int i = (b * 256 + threadIdx.x) * 4;
        const float4 v = *reinterpret_cast<const float4*>(x + i);
        *reinterpret_cast<__half2*>(g_xh + i)     = __floats2half2_rn(v.x, v.y);
        *reinterpret_cast<__half2*>(g_xh + i + 2) = __floats2half2_rn(v.z, v.w);
    } else {
        const size_t i = ((size_t)(b - 2048) * 256 + threadIdx.x) * 4;
        const float4 v = *reinterpret_cast<const float4*>(blocks + i);
        *reinterpret_cast<__half2*>(g_wh + i)     = __floats2half2_rn(v.x, v.y);
        *reinterpret_cast<__half2*>(g_wh + i + 2) = __floats2half2_rn(v.z, v.w);
    }
}

// ---------------- main kernel ----------------
__global__ void __launch_bounds__(THREADS, 2)
mosaic_hmma_kernel(const int* __restrict__ parts,
                   const float* __restrict__ bias,
                   float* __restrict__ out)
{
    extern __shared__ __align__(128) char smem[];
    const uint32_t sb = smem_u32(smem);
    const int tid  = threadIdx.x;
    const int wid  = tid >> 5;
    const int lane = tid & 31;
    const int m0 = blockIdx.y * TM;
    const int n0 = blockIdx.x * TN;
    const int o0 = blockIdx.x * 2;

    const int wm = (wid & 1) * 32;      // 2 warp-rows
    const int wn = (wid >> 1) * 32;     // 4 warp-cols (warp tile 32x32)
    const int lrow = lane & 15;
    const int lcol = (lane >> 4) * 8;

    float acc[2][4][4];
    #pragma unroll
    for (int a = 0; a < 2; ++a)
        #pragma unroll
        for (int b = 0; b < 4; ++b)
            #pragma unroll
            for (int c = 0; c < 4; ++c) acc[a][b][c] = 0.f;

    // cp.async mappings (256 threads, TK=64)
    const int ar = tid >> 3, ac = tid & 7;    // A: rows ar, ar+32 ; col-16B ac
    const int br = tid >> 4, bc = tid & 15;   // B: rows br+16*it (4 it); col-16B bc

    auto issue = [&](int i) {
        if (i < NCHUNK) {
            const int s = i & (NSTAGE - 1);
            const uint32_t abase = sb + s * STAGE_BYTES;
            const uint32_t bbase = abase + A_BYTES;
            const int p0 = parts[i * 128 + o0];
            const int p1 = parts[i * 128 + o0 + 1];
            const size_t k0 = (size_t)i * TK;
            const __half* asrc = g_xh + (size_t)(m0 + ar) * KDIM + k0 + ac * 8;
            cp16(abase + ar * A_STRIDE_B + ac * 16, asrc);
            cp16(abase + (ar + 32) * A_STRIDE_B + ac * 16, asrc + (size_t)32 * KDIM);
            const __half* bsrc = g_wh + ((size_t)((bc < 8) ? p0 : p1) << 12)
                               + br * 64 + (bc & 7) * 8;
            #pragma unroll
            for (int it = 0; it < 4; ++it)
                cp16(bbase + (br + it * 16) * B_STRIDE_B + bc * 16,
                     bsrc + it * 16 * 64);
        }
        asm volatile("cp.async.commit_group;" ::: "memory");
    };

    issue(0); issue(1); issue(2);

    for (int i = 0; i < NCHUNK; ++i) {
        asm volatile("cp.async.wait_group 2;" ::: "memory");
        __syncthreads();
        issue(i + 3);

        const uint32_t abase = sb + (i & (NSTAGE - 1)) * STAGE_BYTES;
        const uint32_t bbase = abase + A_BYTES;
        const uint32_t a_ad = abase + (wm + lrow) * A_STRIDE_B + lcol * 2;
        const uint32_t b_ad = bbase + lrow * B_STRIDE_B + (wn + lcol) * 2;

        // register double-buffered fragments: prefetch kk+1 during mma kk
        uint32_t af[2][2][4], bf[2][2][4];
        ldsm4 (af[0][0], a_ad);
        ldsm4 (af[0][1], a_ad + 16 * A_STRIDE_B);
        ldsm4t(bf[0][0], b_ad);
        ldsm4t(bf[0][1], b_ad + 32);

        #pragma unroll
        for (int kk = 0; kk < 4; ++kk) {
            const int cur = kk & 1, nxt = cur ^ 1;
            if (kk < 3) {
                ldsm4 (af[nxt][0], a_ad + (kk + 1) * 32);
                ldsm4 (af[nxt][1], a_ad + 16 * A_STRIDE_B + (kk + 1) * 32);
                ldsm4t(bf[nxt][0], b_ad + (kk + 1) * 16 * B_STRIDE_B);
                ldsm4t(bf[nxt][1], b_ad + (kk + 1) * 16 * B_STRIDE_B + 32);
            }
            #pragma unroll
            for (int mt = 0; mt < 2; ++mt)
                #pragma unroll
                for (int nt = 0; nt < 2; ++nt) {
                    mma16816(acc[mt][nt * 2 + 0], af[cur][mt], bf[cur][nt][0], bf[cur][nt][1]);
                    mma16816(acc[mt][nt * 2 + 1], af[cur][mt], bf[cur][nt][2], bf[cur][nt][3]);
                }
        }
    }

    // -------- epilogue: bias + store --------
    const int qr = lane >> 2;
    const int qc = (lane & 3) * 2;
    #pragma unroll
    for (int mt = 0; mt < 2; ++mt) {
        const size_t r0 = (size_t)(m0 + wm + mt * 16 + qr);
        #pragma unroll
        for (int nj = 0; nj < 4; ++nj) {
            const int col = n0 + wn + nj * 8 + qc;
            const float2 bv = *reinterpret_cast<const float2*>(bias + col);
            float2 lo, hi;
            lo.x = acc[mt][nj][0] + bv.x;  lo.y = acc[mt][nj][1] + bv.y;
            hi.x = acc[mt][nj][2] + bv.x;  hi.y = acc[mt][nj][3] + bv.y;
            *reinterpret_cast<float2*>(out + r0 * NDIM + col)       = lo;
            *reinterpret_cast<float2*>(out + (r0 + 8) * NDIM + col) = hi;
        }
    }
}

// ---------------- launch ----------------
extern "C" void kernel_launch(void* const* d_in, const int* in_sizes, int n_in,
                              void* d_out, int out_size) {
    const float* x      = (const float*)d_in[0];   // [256, 8192]
    const float* blocks = (const float*)d_in[1];   // [1024, 64, 64]
    const float* bias   = (const float*)d_in[2];   // [8192]
    const int*   parts  = (const int*)d_in[3];     // [128, 128]
    float* out = (float*)d_out;                    // [256, 8192]

    convert_all_kernel<<<6144, 256>>>(x, blocks);

    cudaFuncSetAttribute(mosaic_hmma_kernel,
                         cudaFuncAttributeMaxDynamicSharedMemorySize, SMEM_DYN);
    dim3 grid(NDIM / TN, BROWS / TM);   // (64, 4) = 256 CTAs -> 2 per SM
    mosaic_hmma_kernel<<<grid, THREADS, SMEM_DYN>>>(parts, bias, out);
}